// round 11
// baseline (speedup 1.0000x reference)
#include <cuda_runtime.h>
#include <cuda_fp16.h>
#include <cstdint>

#define T_DIM 2048
#define B_DIM 64
#define I_DIM 256
#define H_DIM 256
#define M_DIM (T_DIM * B_DIM)   /* 131072 */
#define N_DIM (3 * H_DIM)       /* 768    */
#define K_DIM I_DIM             /* 256    */

// ---------------------------------------------------------------------------
// Global scratch (static __device__ arrays: the sanctioned no-alloc path)
// ---------------------------------------------------------------------------
__device__ __align__(256) __half g_gxh[(size_t)M_DIM * N_DIM]; // 201 MB fp16 preacts
__device__ __align__(256) __half g_Bh [(size_t)N_DIM * K_DIM]; // 384 KB fp16 W

// ---------------------------------------------------------------------------
// Baseline-PTX helpers (compute_103-safe: cp.async / ldmatrix / mma.sync only)
// ---------------------------------------------------------------------------
__device__ __forceinline__ uint32_t smem_u32(const void* p) {
    uint32_t a;
    asm("{ .reg .u64 t; cvta.to.shared.u64 t, %1; cvt.u32.u64 %0, t; }"
        : "=r"(a) : "l"(p));
    return a;
}
__device__ __forceinline__ void cp_async16(uint32_t dst, const void* src) {
    asm volatile("cp.async.cg.shared.global [%0], [%1], 16;"
                 :: "r"(dst), "l"(src) : "memory");
}
__device__ __forceinline__ void cp_commit() {
    asm volatile("cp.async.commit_group;" ::: "memory");
}
template<int N> __device__ __forceinline__ void cp_wait() {
    asm volatile("cp.async.wait_group %0;" :: "n"(N) : "memory");
}
__device__ __forceinline__ void ldsm4(uint32_t r[4], uint32_t addr) {
    asm volatile("ldmatrix.sync.aligned.m8n8.x4.shared.b16 {%0,%1,%2,%3}, [%4];"
                 : "=r"(r[0]), "=r"(r[1]), "=r"(r[2]), "=r"(r[3]) : "r"(addr));
}
__device__ __forceinline__ void mma16816(float c[4], const uint32_t a[4],
                                         const uint32_t b0, const uint32_t b1) {
    asm volatile("mma.sync.aligned.m16n8k16.row.col.f32.f16.f16.f32 "
                 "{%0,%1,%2,%3}, {%4,%5,%6,%7}, {%8,%9}, {%0,%1,%2,%3};"
                 : "+f"(c[0]), "+f"(c[1]), "+f"(c[2]), "+f"(c[3])
                 : "r"(a[0]), "r"(a[1]), "r"(a[2]), "r"(a[3]), "r"(b0), "r"(b1));
}
__device__ __forceinline__ float tanh_fast(float x) {
    float y;
    asm("tanh.approx.f32 %0, %1;" : "=f"(y) : "f"(x));
    return y;
}
__device__ __forceinline__ uint32_t swz(uint32_t b) { return b ^ ((b >> 3) & 0x70); }

// ---------------------------------------------------------------------------
// fp32 -> fp16 conversion for W_ih only (384 KB, ~3us)
// ---------------------------------------------------------------------------
__global__ void tohalf_kernel(const float4* __restrict__ src, int n4)
{
    int i = blockIdx.x * blockDim.x + threadIdx.x;
    if (i >= n4) return;
    float4 v = src[i];
    __half2* p = (__half2*)(g_Bh + (size_t)i * 4);
    p[0] = __floats2half2_rn(v.x, v.y);
    p[1] = __floats2half2_rn(v.z, v.w);
}

// ---------------------------------------------------------------------------
// Fused-convert fp16 HMMA GEMM:  gx[m,n] = sum_k x[m,k] W[n,k] + bias[n]
// A arrives as fp32 via cp.async (no separate convert kernel); in-kernel
// convert to the SW128 fp16 buffer, then the verified ldsm/mma path.
// CTA 128x128, BK=64, 8 warps (warp tile 32x64), double-buffered everything:
// A32 2x32K + A16 2x16K + B 2x16K = 128 KB, 1 CTA/SM. fp32 acc, fp16 out.
// ---------------------------------------------------------------------------
#define BM 128
#define BN 128
#define BK 64
#define NCHUNK (K_DIM / BK)      /* 4 */

#define A32_OFF 0                /* 2 x 32768 */
#define A16_OFF 65536            /* 2 x 16384 */
#define BH_OFF  98304            /* 2 x 16384 */
#define GEMM_SMEM 131072

__global__ __launch_bounds__(256, 1)
void indgru_hmma_gemm(const float* __restrict__ A,
                      const float* __restrict__ bias)
{
    extern __shared__ char dyn_smem[];
    const uint32_t sb = smem_u32(dyn_smem);

    const int tid = threadIdx.x;
    const int bn  = blockIdx.x * BN;          // 6 N-tiles (x fastest -> A L2 reuse)
    const int bm  = blockIdx.y * BM;          // 1024 M-tiles

    const int warp   = tid >> 5;
    const int lane   = tid & 31;
    const int warp_m = warp >> 1;             // 0..3 -> 32-row slice
    const int warp_n = warp & 1;              // 0..1 -> 64-col slice
    const int r      = lane & 7;
    const int q      = lane >> 3;

    // ---- per-lane ldmatrix row bases (verified round 4) ----
    uint32_t aRow[2], aXor[2];
#pragma unroll
    for (int mt = 0; mt < 2; mt++) {
        int row = warp_m * 32 + mt * 16 + (q & 1) * 8 + r;
        aRow[mt] = row * 128;
        aXor[mt] = (row & 7) * 16;
    }
    const uint32_t aK = (q >> 1) * 16;
    uint32_t bRow[4], bXor[4];
#pragma unroll
    for (int p = 0; p < 4; p++) {
        int row = warp_n * 64 + p * 16 + (q >> 1) * 8 + r;
        bRow[p] = row * 128;
        bXor[p] = (row & 7) * 16;
    }
    const uint32_t bK = (q & 1) * 16;

    float acc[2][8][4];
#pragma unroll
    for (int mt = 0; mt < 2; mt++)
#pragma unroll
        for (int t = 0; t < 8; t++)
#pragma unroll
            for (int e = 0; e < 4; e++) acc[mt][t][e] = 0.f;

    // ---- chunk loader: A fp32 (8 x 16B) + B fp16 (4 x 16B) per thread ----
    auto load_chunk = [&](int c) {
        const uint32_t a32  = sb + A32_OFF + (uint32_t)(c & 1) * 32768;
        const uint32_t bbuf = sb + BH_OFF  + (uint32_t)(c & 1) * 16384;
        const int kc = c * BK;
#pragma unroll
        for (int i = 0; i < 8; i++) {         // A32: 128 rows x 16 x 16B
            int cid = tid + i * 256;          // 0..2047
            int row = cid >> 4, c16 = cid & 15;
            cp_async16(a32 + (uint32_t)(row * 256 + c16 * 16),
                       A + (size_t)(bm + row) * K_DIM + kc + c16 * 4);
        }
#pragma unroll
        for (int i = 0; i < 4; i++) {         // B: 128 rows x 8 x 16B
            int cid = tid + i * 256;
            int row = cid >> 3, c8 = cid & 7;
            cp_async16(bbuf + swz((uint32_t)(row * 128 + c8 * 16)),
                       g_Bh + (size_t)(bn + row) * K_DIM + kc + c8 * 8);
        }
        cp_commit();
    };

    // ---- in-kernel fp32 -> fp16 convert into SW128 layout ----
    auto convert = [&](int c) {
        const uint32_t a32 = sb + A32_OFF + (uint32_t)(c & 1) * 32768;
        const uint32_t a16 = sb + A16_OFF + (uint32_t)(c & 1) * 16384;
#pragma unroll
        for (int i = 0; i < 8; i++) {
            int cid = tid + i * 256;
            int row = cid >> 4, c16 = cid & 15;
            float vx, vy, vz, vw;
            asm volatile("ld.shared.v4.f32 {%0,%1,%2,%3}, [%4];"
                         : "=f"(vx), "=f"(vy), "=f"(vz), "=f"(vw)
                         : "r"(a32 + (uint32_t)(row * 256 + c16 * 16)));
            __half2 h0 = __floats2half2_rn(vx, vy);
            __half2 h1 = __floats2half2_rn(vz, vw);
            uint32_t u0 = *(uint32_t*)&h0, u1 = *(uint32_t*)&h1;
            asm volatile("st.shared.v2.b32 [%0], {%1,%2};"
                         :: "r"(a16 + swz((uint32_t)(row * 128 + c16 * 8))),
                            "r"(u0), "r"(u1) : "memory");
        }
    };

    auto compute = [&](int c) {
        const uint32_t a16  = sb + A16_OFF + (uint32_t)(c & 1) * 16384;
        const uint32_t bbuf = sb + BH_OFF  + (uint32_t)(c & 1) * 16384;
#pragma unroll
        for (int ks = 0; ks < 4; ks++) {
            const uint32_t k2 = ks * 32;
            uint32_t Ah[2][4], Bh[4][4];
#pragma unroll
            for (int mt = 0; mt < 2; mt++)
                ldsm4(Ah[mt], a16 + aRow[mt] + ((k2 + aK) ^ aXor[mt]));
#pragma unroll
            for (int p = 0; p < 4; p++)
                ldsm4(Bh[p], bbuf + bRow[p] + ((k2 + bK) ^ bXor[p]));
#pragma unroll
            for (int mt = 0; mt < 2; mt++)
#pragma unroll
                for (int p = 0; p < 4; p++) {
                    mma16816(acc[mt][2*p],   Ah[mt], Bh[p][0], Bh[p][1]);
                    mma16816(acc[mt][2*p+1], Ah[mt], Bh[p][2], Bh[p][3]);
                }
        }
    };

    load_chunk(0); load_chunk(1);
#pragma unroll
    for (int c = 0; c < NCHUNK; c++) {
        if (c < NCHUNK - 1) cp_wait<1>(); else cp_wait<0>();
        __syncthreads();                      // chunk c visible to all threads
        convert(c);
        __syncthreads();                      // A16(c) visible before ldsm
        compute(c);
        if (c + 2 < NCHUNK) {
            __syncthreads();                  // all warps done with buf (c&1)
            load_chunk(c + 2);
        }
    }

    // ---- epilogue: +bias, convert fp16, store ----
    const int mrow = bm + warp_m * 32 + (lane >> 2);
    const int ncol = bn + warp_n * 64 + (lane & 3) * 2;
#pragma unroll
    for (int t = 0; t < 8; t++) {
        const int n = ncol + t * 8;
        const float b0 = __ldg(bias + n), b1 = __ldg(bias + n + 1);
#pragma unroll
        for (int mt = 0; mt < 2; mt++) {
            __half* p0 = g_gxh + (size_t)(mrow + mt * 16) * N_DIM + n;
            __half* p1 = p0 + 8 * N_DIM;
            *(__half2*)p0 = __floats2half2_rn(acc[mt][t][0] + b0, acc[mt][t][1] + b1);
            *(__half2*)p1 = __floats2half2_rn(acc[mt][t][2] + b0, acc[mt][t][3] + b1);
        }
    }
}

// ---------------------------------------------------------------------------
// Diagonal GRU scan, fp16 cp.async ring, shortened 44-cyc dependent chain:
//   pr = fma(whr/2, h, (xr+bhr)/2) -> tanh -> pn = fma(t/2, tr, xn+t/2)
//   -> tanh -> h' = fma(zb, tn, zh)   (z-chain runs in parallel)
// 256 blocks x 64 threads; CS=16 steps/chunk (128 barriers), NS=8 ring (48KB),
// 112 steps of cp.async prefetch in flight.
// ---------------------------------------------------------------------------
#define CS 16                      /* steps per chunk  */
#define NS 8                       /* ring stages      */
#define NCH (T_DIM / CS)           /* 128 chunks       */
#define JW 64                      /* j-width per block */
#define CHUNK_HALFS (CS * 3 * JW)  /* 3072 */
#define SCAN_SMEM (NS * CHUNK_HALFS * 2)    /* 49152 */

__global__ __launch_bounds__(64)
void indgru_scan_kernel(const float* __restrict__ w_hh,
                        const float* __restrict__ b_hh,
                        float* __restrict__ out)
{
    extern __shared__ __half ringh[];        // [NS][CS][3][JW]
    const uint32_t ring_b = smem_u32(ringh);

    const int tx    = threadIdx.x;           // 0..63
    const int b     = blockIdx.x >> 2;
    const int jbase = (blockIdx.x & 3) * JW;
    const int j     = jbase + tx;

    const float whr2 = 0.5f * w_hh[j];
    const float whz2 = 0.5f * w_hh[H_DIM + j];
    const float whn  = w_hh[2 * H_DIM + j];
    const float bhr2 = 0.5f * b_hh[j];
    const float bhz2 = 0.5f * b_hh[H_DIM + j];
    const float bhn  = b_hh[2 * H_DIM + j];

    const __half* gbase = g_gxh + (size_t)b * N_DIM + jbase;

    // per-chunk loader: 48 rows of (step,gate) x 128B = 384 16B ops, 6/thread
    auto load_chunk = [&](int ci) {
        if (ci < NCH) {
            const __half* cb = gbase + (size_t)ci * CS * (B_DIM * N_DIM);
            const uint32_t d0 = ring_b + (uint32_t)(ci & (NS - 1)) * (CHUNK_HALFS * 2);
#pragma unroll
            for (int i = 0; i < 6; i++) {
                int cid  = tx + i * 64;       // 0..383
                int row  = cid >> 3;          // 0..47 = step*3+gate
                int sub  = cid & 7;           // 16B sub-chunk (8 halfs)
                int step = row / 3, gate = row % 3;
                cp_async16(d0 + (uint32_t)(row * 128 + sub * 16),
                           cb + (size_t)step * (B_DIM * N_DIM) + gate * H_DIM + sub * 8);
            }
        }
        cp_commit();                          // uniform group count past the end
    };

#pragma unroll
    for (int c = 0; c < NS - 1; c++) load_chunk(c);   // 7 chunks in flight

    float h = 0.f;
    float* op = out + b * H_DIM + j;

#define GRU_STEP(xr, xz, xn)                                     \
    do {                                                         \
        float cr = fmaf(0.5f, (xr), bhr2);                       \
        float cz = fmaf(0.5f, (xz), bhz2);                       \
        float pr = fmaf(whr2, h, cr);          /* chain +4  */   \
        float pz = fmaf(whz2, h, cz);          /* parallel  */   \
        float tr = tanh_fast(pr);              /* chain +16 */   \
        float tz = tanh_fast(pz);              /* parallel  */   \
        float t  = fmaf(whn, h, bhn);          /* parallel  */   \
        float ht = 0.5f * t;                                     \
        float cn = ht + (xn);                                    \
        float pn = fmaf(ht, tr, cn);           /* chain +4  */   \
        float tn = tanh_fast(pn);              /* chain +16 */   \
        float zh = 0.5f * fmaf(tz, h, h);      /* parallel  */   \
        float zb = fmaf(-0.5f, tz, 0.5f);      /* parallel  */   \
        h = fmaf(zb, tn, zh);                  /* chain +4  */   \
    } while (0)

    for (int ci = 0; ci < NCH; ci++) {
        cp_wait<NS - 2>();                    // chunk ci fully arrived
        __syncthreads();
        const __half* st = ringh + (ci & (NS - 1)) * CHUNK_HALFS;
#pragma unroll
        for (int s = 0; s < CS; s++) {
            const float xr = __half2float(st[(s * 3 + 0) * JW + tx]);
            const float xz = __half2float(st[(s * 3 + 1) * JW + tx]);
            const float xn = __half2float(st[(s * 3 + 2) * JW + tx]);
            GRU_STEP(xr, xz, xn);
            *op = h;
            op += B_DIM * H_DIM;
        }
        load_chunk(ci + NS - 1);
    }
    *op = h;                                  // h_n[0, b, j]
#undef GRU_STEP
}

// ---------------------------------------------------------------------------
extern "C" void kernel_launch(void* const* d_in, const int* in_sizes, int n_in,
                              void* d_out, int out_size)
{
    const float* x    = (const float*)d_in[0];   // [T, B, I]
    const float* W_ih = (const float*)d_in[1];   // [3H, I]
    const float* b_ih = (const float*)d_in[2];   // [3H]
    const float* b_hh = (const float*)d_in[3];   // [3H]
    const float* w_hh = (const float*)d_in[4];   // [3, H]
    float* out = (float*)d_out;

    cudaFuncSetAttribute(indgru_hmma_gemm,
                         cudaFuncAttributeMaxDynamicSharedMemorySize, GEMM_SMEM);
    cudaFuncSetAttribute(indgru_scan_kernel,
                         cudaFuncAttributeMaxDynamicSharedMemorySize, SCAN_SMEM);

    {   // W_ih fp32 -> fp16 (tiny)
        int w4 = N_DIM * K_DIM / 4;
        tohalf_kernel<<<(w4 + 255) / 256, 256>>>((const float4*)W_ih, w4);
    }

    dim3 grid(N_DIM / BN, M_DIM / BM);   // (6, 1024)
    indgru_hmma_gemm<<<grid, 256, GEMM_SMEM>>>(x, b_ih);

    indgru_scan_kernel<<<4 * B_DIM, 64, SCAN_SMEM>>>(w_hh, b_hh, out);
}

// round 12
// speedup vs baseline: 1.9228x; 1.9228x over previous
#include <cuda_runtime.h>
#include <cuda_fp16.h>
#include <cstdint>

#define T_DIM 2048
#define B_DIM 64
#define I_DIM 256
#define H_DIM 256
#define M_DIM (T_DIM * B_DIM)   /* 131072 */
#define N_DIM (3 * H_DIM)       /* 768    */
#define K_DIM I_DIM             /* 256    */

// ---------------------------------------------------------------------------
// Global scratch (static __device__ arrays: the sanctioned no-alloc path)
// ---------------------------------------------------------------------------
__device__ __align__(256) __half g_gxh[(size_t)M_DIM * N_DIM]; // 201 MB fp16 preacts
__device__ __align__(256) __half g_Ah [(size_t)M_DIM * K_DIM]; // 64 MB
__device__ __align__(256) __half g_Bh [(size_t)N_DIM * K_DIM]; // 384 KB

// ---------------------------------------------------------------------------
// Baseline-PTX helpers (compute_103-safe: cp.async / ldmatrix / mma.sync only)
// ---------------------------------------------------------------------------
__device__ __forceinline__ uint32_t smem_u32(const void* p) {
    uint32_t a;
    asm("{ .reg .u64 t; cvta.to.shared.u64 t, %1; cvt.u32.u64 %0, t; }"
        : "=r"(a) : "l"(p));
    return a;
}
__device__ __forceinline__ void cp_async16(uint32_t dst, const void* src) {
    asm volatile("cp.async.cg.shared.global [%0], [%1], 16;"
                 :: "r"(dst), "l"(src) : "memory");
}
__device__ __forceinline__ void cp_commit() {
    asm volatile("cp.async.commit_group;" ::: "memory");
}
template<int N> __device__ __forceinline__ void cp_wait() {
    asm volatile("cp.async.wait_group %0;" :: "n"(N) : "memory");
}
__device__ __forceinline__ void ldsm4(uint32_t r[4], uint32_t addr) {
    asm volatile("ldmatrix.sync.aligned.m8n8.x4.shared.b16 {%0,%1,%2,%3}, [%4];"
                 : "=r"(r[0]), "=r"(r[1]), "=r"(r[2]), "=r"(r[3]) : "r"(addr));
}
__device__ __forceinline__ void mma16816(float c[4], const uint32_t a[4],
                                         const uint32_t b0, const uint32_t b1) {
    asm volatile("mma.sync.aligned.m16n8k16.row.col.f32.f16.f16.f32 "
                 "{%0,%1,%2,%3}, {%4,%5,%6,%7}, {%8,%9}, {%0,%1,%2,%3};"
                 : "+f"(c[0]), "+f"(c[1]), "+f"(c[2]), "+f"(c[3])
                 : "r"(a[0]), "r"(a[1]), "r"(a[2]), "r"(a[3]), "r"(b0), "r"(b1));
}
__device__ __forceinline__ float tanh_fast(float x) {
    float y;
    asm("tanh.approx.f32 %0, %1;" : "=f"(y) : "f"(x));
    return y;
}
__device__ __forceinline__ uint32_t swz(uint32_t b) { return b ^ ((b >> 3) & 0x70); }

// ---------------------------------------------------------------------------
// fp32 -> fp16 conversion.  which=0 -> A (x), 1 -> B (W_ih).
// ---------------------------------------------------------------------------
__global__ void tohalf_kernel(const float4* __restrict__ src, int n4, int which)
{
    int i = blockIdx.x * blockDim.x + threadIdx.x;
    if (i >= n4) return;
    __half* dst = which ? g_Bh : g_Ah;
    float4 v = src[i];
    __half2* p = (__half2*)(dst + (size_t)i * 4);
    p[0] = __floats2half2_rn(v.x, v.y);
    p[1] = __floats2half2_rn(v.z, v.w);
}

// ---------------------------------------------------------------------------
// Single-pass fp16 HMMA GEMM (round-10 verified config):
// CTA 128x128, BK=64 (128B rows, SW128 swizzle), 8 warps (warp tile 32x64),
// 32KB/stage, 3-stage cp.async ring, 2 CTAs/SM. fp32 accumulate, fp16 out.
// ---------------------------------------------------------------------------
#define BM 128
#define BN 128
#define BK 64
#define NCHUNK (K_DIM / BK)      /* 4 */

#define AH_OFF 0
#define BH_OFF 16384
#define STAGE_BYTES 32768        /* 32 KB */
#define GEMM_SMEM (3 * STAGE_BYTES)

__global__ __launch_bounds__(256, 2)
void indgru_hmma_gemm(const float* __restrict__ bias)
{
    extern __shared__ char dyn_smem[];
    const uint32_t sb = smem_u32(dyn_smem);

    const int tid = threadIdx.x;
    const int bn  = blockIdx.x * BN;          // 6 N-tiles (x fastest -> A L2 reuse)
    const int bm  = blockIdx.y * BM;          // 1024 M-tiles

    const int warp   = tid >> 5;
    const int lane   = tid & 31;
    const int warp_m = warp >> 1;             // 0..3 -> 32-row slice
    const int warp_n = warp & 1;              // 0..1 -> 64-col slice
    const int r      = lane & 7;
    const int q      = lane >> 3;

    // ---- per-lane ldmatrix row bases (verified round 4) ----
    uint32_t aRow[2], aXor[2];
#pragma unroll
    for (int mt = 0; mt < 2; mt++) {
        int row = warp_m * 32 + mt * 16 + (q & 1) * 8 + r;
        aRow[mt] = row * 128;
        aXor[mt] = (row & 7) * 16;
    }
    const uint32_t aK = (q >> 1) * 16;
    uint32_t bRow[4], bXor[4];
#pragma unroll
    for (int p = 0; p < 4; p++) {
        int row = warp_n * 64 + p * 16 + (q >> 1) * 8 + r;
        bRow[p] = row * 128;
        bXor[p] = (row & 7) * 16;
    }
    const uint32_t bK = (q & 1) * 16;

    float acc[2][8][4];
#pragma unroll
    for (int mt = 0; mt < 2; mt++)
#pragma unroll
        for (int t = 0; t < 8; t++)
#pragma unroll
            for (int e = 0; e < 4; e++) acc[mt][t][e] = 0.f;

    // ---- chunk loader: 8 cp.async(16B) per thread ----
    auto load_chunk = [&](int c) {
        const uint32_t st = sb + (uint32_t)(c % 3) * STAGE_BYTES;
        const int kc = c * BK;
#pragma unroll
        for (int i = 0; i < 4; i++) {         // A: 128 rows x 8 x 16B
            int cid = tid + i * 256;
            int row = cid >> 3, c16 = cid & 7;
            uint32_t off = swz((uint32_t)(row * 128 + c16 * 16));
            cp_async16(st + AH_OFF + off,
                       g_Ah + (size_t)(bm + row) * K_DIM + kc + c16 * 8);
        }
#pragma unroll
        for (int i = 0; i < 4; i++) {         // B: 128 rows x 8 x 16B
            int cid = tid + i * 256;
            int row = cid >> 3, c16 = cid & 7;
            uint32_t off = swz((uint32_t)(row * 128 + c16 * 16));
            cp_async16(st + BH_OFF + off,
                       g_Bh + (size_t)(bn + row) * K_DIM + kc + c16 * 8);
        }
        cp_commit();
    };

    auto compute = [&](int c) {
        const uint32_t st = sb + (uint32_t)(c % 3) * STAGE_BYTES;
#pragma unroll
        for (int ks = 0; ks < 4; ks++) {
            const uint32_t k2 = ks * 32;
            uint32_t Ah[2][4], Bh[4][4];
#pragma unroll
            for (int mt = 0; mt < 2; mt++)
                ldsm4(Ah[mt], st + AH_OFF + aRow[mt] + ((k2 + aK) ^ aXor[mt]));
#pragma unroll
            for (int p = 0; p < 4; p++)
                ldsm4(Bh[p], st + BH_OFF + bRow[p] + ((k2 + bK) ^ bXor[p]));
#pragma unroll
            for (int mt = 0; mt < 2; mt++)
#pragma unroll
                for (int p = 0; p < 4; p++) {
                    mma16816(acc[mt][2*p],   Ah[mt], Bh[p][0], Bh[p][1]);
                    mma16816(acc[mt][2*p+1], Ah[mt], Bh[p][2], Bh[p][3]);
                }
        }
    };

    load_chunk(0); load_chunk(1); load_chunk(2);
    cp_wait<2>(); __syncthreads();
    compute(0);
    __syncthreads();
    load_chunk(3);
    cp_wait<2>(); __syncthreads();
    compute(1);
    cp_wait<1>(); __syncthreads();
    compute(2);
    cp_wait<0>(); __syncthreads();
    compute(3);

    // ---- epilogue: +bias, convert fp16, store ----
    const int mrow = bm + warp_m * 32 + (lane >> 2);
    const int ncol = bn + warp_n * 64 + (lane & 3) * 2;
#pragma unroll
    for (int t = 0; t < 8; t++) {
        const int n = ncol + t * 8;
        const float b0 = __ldg(bias + n), b1 = __ldg(bias + n + 1);
#pragma unroll
        for (int mt = 0; mt < 2; mt++) {
            __half* p0 = g_gxh + (size_t)(mrow + mt * 16) * N_DIM + n;
            __half* p1 = p0 + 8 * N_DIM;
            *(__half2*)p0 = __floats2half2_rn(acc[mt][t][0] + b0, acc[mt][t][1] + b1);
            *(__half2*)p1 = __floats2half2_rn(acc[mt][t][2] + b0, acc[mt][t][3] + b1);
        }
    }
}

// ---------------------------------------------------------------------------
// Diagonal GRU scan, fp16 cp.async ring, shortened 44-cyc dependent chain:
//   r/z pre-activations halved into tanh form; n-gate folds r via one fma;
//   blend h' = fma(zb, tn, zh) with zb/zh off-chain.
// 256 blocks x 64 threads; CS=16 steps/chunk (128 wait/bar pairs), NS=8 ring
// (48 KB), 112 steps of cp.async prefetch in flight.
// ---------------------------------------------------------------------------
#define CS 16                      /* steps per chunk  */
#define NS 8                       /* ring stages      */
#define NCH (T_DIM / CS)           /* 128 chunks       */
#define JW 64                      /* j-width per block */
#define CHUNK_HALFS (CS * 3 * JW)  /* 3072 */
#define SCAN_SMEM (NS * CHUNK_HALFS * 2)    /* 49152 */

__global__ __launch_bounds__(64)
void indgru_scan_kernel(const float* __restrict__ w_hh,
                        const float* __restrict__ b_hh,
                        float* __restrict__ out)
{
    extern __shared__ __half ringh[];        // [NS][CS][3][JW]
    const uint32_t ring_b = smem_u32(ringh);

    const int tx    = threadIdx.x;           // 0..63
    const int b     = blockIdx.x >> 2;
    const int jbase = (blockIdx.x & 3) * JW;
    const int j     = jbase + tx;

    const float whr2 = 0.5f * w_hh[j];
    const float whz2 = 0.5f * w_hh[H_DIM + j];
    const float whn  = w_hh[2 * H_DIM + j];
    const float bhr2 = 0.5f * b_hh[j];
    const float bhz2 = 0.5f * b_hh[H_DIM + j];
    const float bhn  = b_hh[2 * H_DIM + j];

    const __half* gbase = g_gxh + (size_t)b * N_DIM + jbase;

    // per-chunk loader: 48 rows of (step,gate) x 128B = 384 16B ops, 6/thread
    auto load_chunk = [&](int ci) {
        if (ci < NCH) {
            const __half* cb = gbase + (size_t)ci * CS * (B_DIM * N_DIM);
            const uint32_t d0 = ring_b + (uint32_t)(ci & (NS - 1)) * (CHUNK_HALFS * 2);
#pragma unroll
            for (int i = 0; i < 6; i++) {
                int cid  = tx + i * 64;       // 0..383
                int row  = cid >> 3;          // 0..47 = step*3+gate
                int sub  = cid & 7;           // 16B sub-chunk (8 halfs)
                int step = row / 3, gate = row % 3;
                cp_async16(d0 + (uint32_t)(row * 128 + sub * 16),
                           cb + (size_t)step * (B_DIM * N_DIM) + gate * H_DIM + sub * 8);
            }
        }
        cp_commit();                          // uniform group count past the end
    };

#pragma unroll
    for (int c = 0; c < NS - 1; c++) load_chunk(c);   // 7 chunks in flight

    float h = 0.f;
    float* op = out + b * H_DIM + j;

#define GRU_STEP(xr, xz, xn)                                     \
    do {                                                         \
        float cr = fmaf(0.5f, (xr), bhr2);                       \
        float cz = fmaf(0.5f, (xz), bhz2);                       \
        float pr = fmaf(whr2, h, cr);          /* chain +4  */   \
        float pz = fmaf(whz2, h, cz);          /* parallel  */   \
        float tr = tanh_fast(pr);              /* chain +16 */   \
        float tz = tanh_fast(pz);              /* parallel  */   \
        float t  = fmaf(whn, h, bhn);          /* parallel  */   \
        float ht = 0.5f * t;                                     \
        float cn = ht + (xn);                                    \
        float pn = fmaf(ht, tr, cn);           /* chain +4  */   \
        float tn = tanh_fast(pn);              /* chain +16 */   \
        float zh = 0.5f * fmaf(tz, h, h);      /* parallel  */   \
        float zb = fmaf(-0.5f, tz, 0.5f);      /* parallel  */   \
        h = fmaf(zb, tn, zh);                  /* chain +4  */   \
    } while (0)

    for (int ci = 0; ci < NCH; ci++) {
        cp_wait<NS - 2>();                    // chunk ci fully arrived
        __syncthreads();
        const __half* st = ringh + (ci & (NS - 1)) * CHUNK_HALFS;
#pragma unroll
        for (int s = 0; s < CS; s++) {
            const float xr = __half2float(st[(s * 3 + 0) * JW + tx]);
            const float xz = __half2float(st[(s * 3 + 1) * JW + tx]);
            const float xn = __half2float(st[(s * 3 + 2) * JW + tx]);
            GRU_STEP(xr, xz, xn);
            *op = h;
            op += B_DIM * H_DIM;
        }
        load_chunk(ci + NS - 1);
    }
    *op = h;                                  // h_n[0, b, j]
#undef GRU_STEP
}

// ---------------------------------------------------------------------------
extern "C" void kernel_launch(void* const* d_in, const int* in_sizes, int n_in,
                              void* d_out, int out_size)
{
    const float* x    = (const float*)d_in[0];   // [T, B, I]
    const float* W_ih = (const float*)d_in[1];   // [3H, I]
    const float* b_ih = (const float*)d_in[2];   // [3H]
    const float* b_hh = (const float*)d_in[3];   // [3H]
    const float* w_hh = (const float*)d_in[4];   // [3, H]
    float* out = (float*)d_out;

    cudaFuncSetAttribute(indgru_hmma_gemm,
                         cudaFuncAttributeMaxDynamicSharedMemorySize, GEMM_SMEM);
    cudaFuncSetAttribute(indgru_scan_kernel,
                         cudaFuncAttributeMaxDynamicSharedMemorySize, SCAN_SMEM);

    {   // fp32 -> fp16
        int n4 = M_DIM * K_DIM / 4;
        tohalf_kernel<<<(n4 + 255) / 256, 256>>>((const float4*)x, n4, 0);
        int w4 = N_DIM * K_DIM / 4;
        tohalf_kernel<<<(w4 + 255) / 256, 256>>>((const float4*)W_ih, w4, 1);
    }

    dim3 grid(N_DIM / BN, M_DIM / BM);   // (6, 1024)
    indgru_hmma_gemm<<<grid, 256, GEMM_SMEM>>>(b_ih);

    indgru_scan_kernel<<<4 * B_DIM, 64, SCAN_SMEM>>>(w_hh, b_hh, out);
}